// round 1
// baseline (speedup 1.0000x reference)
#include <cuda_runtime.h>
#include <math.h>

#define NMAX 50176
#define EMAX 800000

// ---- device scratch (no runtime allocation allowed) ----
__device__ float g_xl[NMAX * 128];
__device__ float g_xr[NMAX * 128];
__device__ float g_h [NMAX * 128];
__device__ int   g_counts[NMAX];
__device__ int   g_rowptr[NMAX + 1];
__device__ int   g_cursor[NMAX];
__device__ int   g_csrc  [EMAX];

// ---------------- CSR build ----------------
__global__ void k_zero_counts(int n) {
    int i = blockIdx.x * blockDim.x + threadIdx.x;
    if (i < n) g_counts[i] = 0;
}

__global__ void k_hist(const int* __restrict__ ei, int E) {
    int e = blockIdx.x * blockDim.x + threadIdx.x;
    if (e < E) atomicAdd(&g_counts[ei[E + e]], 1);
}

__global__ void k_scan(int n) {
    __shared__ int part[1024];
    int tid = threadIdx.x;
    int chunk = (n + 1023) >> 10;
    int s0 = tid * chunk;
    int s1 = min(s0 + chunk, n);
    int s = 0;
    for (int i = s0; i < s1; i++) s += g_counts[i];
    part[tid] = s;
    __syncthreads();
    // Hillis-Steele inclusive scan
    for (int off = 1; off < 1024; off <<= 1) {
        int v = (tid >= off) ? part[tid - off] : 0;
        __syncthreads();
        part[tid] += v;
        __syncthreads();
    }
    int base = (tid == 0) ? 0 : part[tid - 1];
    for (int i = s0; i < s1; i++) {
        g_rowptr[i] = base;
        g_cursor[i] = base;
        base += g_counts[i];
    }
    if (s1 == n) g_rowptr[n] = base;  // all qualifying threads write same total
}

__global__ void k_scatter(const int* __restrict__ ei, int E) {
    int e = blockIdx.x * blockDim.x + threadIdx.x;
    if (e < E) {
        int d = ei[E + e];
        int pos = atomicAdd(&g_cursor[d], 1);
        g_csrc[pos] = ei[e];
    }
}

// ---------------- GEMM: C[M,128] = A[M,128] @ W[128,128] + bias ----------------
__global__ __launch_bounds__(256) void k_gemm128(
    const float* __restrict__ A, const float* __restrict__ W,
    const float* __restrict__ bias, float* __restrict__ C, int M)
{
    __shared__ float As[64][16];     // [m][k]
    __shared__ float Ws[16][128];    // [k][n]
    int tid = threadIdx.x;
    int row0 = blockIdx.x << 6;

    int tr = (tid >> 4) << 2;        // 0..60 step 4
    int tc = (tid & 15) << 3;        // 0..120 step 8

    int a_m = tid >> 2;              // 0..63
    int a_k = (tid & 3) << 2;        // 0,4,8,12
    int w_r = tid >> 5;              // 0..7
    int w_c = (tid & 31) << 2;       // 0..124

    float acc[4][8];
#pragma unroll
    for (int i = 0; i < 4; i++)
#pragma unroll
        for (int j = 0; j < 8; j++) acc[i][j] = 0.f;

    for (int k0 = 0; k0 < 128; k0 += 16) {
        float4 av = make_float4(0.f, 0.f, 0.f, 0.f);
        int gm = row0 + a_m;
        if (gm < M) av = *(const float4*)(A + (size_t)gm * 128 + k0 + a_k);
        float4 w0 = *(const float4*)(W + (size_t)(k0 + w_r) * 128 + w_c);
        float4 w1 = *(const float4*)(W + (size_t)(k0 + w_r + 8) * 128 + w_c);
        __syncthreads();
        *(float4*)&As[a_m][a_k]     = av;
        *(float4*)&Ws[w_r][w_c]     = w0;
        *(float4*)&Ws[w_r + 8][w_c] = w1;
        __syncthreads();
#pragma unroll
        for (int k = 0; k < 16; k++) {
            float a[4];
#pragma unroll
            for (int i = 0; i < 4; i++) a[i] = As[tr + i][k];
            float4 b0 = *(const float4*)&Ws[k][tc];
            float4 b1 = *(const float4*)&Ws[k][tc + 4];
            float b[8] = {b0.x, b0.y, b0.z, b0.w, b1.x, b1.y, b1.z, b1.w};
#pragma unroll
            for (int i = 0; i < 4; i++)
#pragma unroll
                for (int j = 0; j < 8; j++)
                    acc[i][j] = fmaf(a[i], b[j], acc[i][j]);
        }
    }

    float4 bv0 = *(const float4*)(bias + tc);
    float4 bv1 = *(const float4*)(bias + tc + 4);
#pragma unroll
    for (int i = 0; i < 4; i++) {
        int gm = row0 + tr + i;
        if (gm < M) {
            float4 o0 = make_float4(acc[i][0] + bv0.x, acc[i][1] + bv0.y,
                                    acc[i][2] + bv0.z, acc[i][3] + bv0.w);
            float4 o1 = make_float4(acc[i][4] + bv1.x, acc[i][5] + bv1.y,
                                    acc[i][6] + bv1.z, acc[i][7] + bv1.w);
            *(float4*)(C + (size_t)gm * 128 + tc)     = o0;
            *(float4*)(C + (size_t)gm * 128 + tc + 4) = o1;
        }
    }
}

// ---------------- GATv2 aggregation: one warp per destination node ----------------
// Lane l holds channels [4l, 4l+3]. Layer1: head = l/8, logit reduce within
// 8-lane groups (3 shfl). Layer2: heads=1, full-warp reduce (5 shfl).
// Single-pass online softmax; self-loop processed first; CSR neighbors after.
template<bool FULLWARP, bool DOELU>
__global__ __launch_bounds__(256) void k_agg(
    const float* __restrict__ xl, const float* __restrict__ xr,
    const float* __restrict__ att, const float* __restrict__ bias,
    float* __restrict__ out, int n)
{
    int gw = (blockIdx.x * blockDim.x + threadIdx.x) >> 5;
    if (gw >= n) return;
    int lane = threadIdx.x & 31;
    int node = gw;

    float4 attv = *(const float4*)(att + (lane << 2));
    float4 xrv  = *(const float4*)(xr + (size_t)node * 128 + (lane << 2));

    int beg = g_rowptr[node];
    int end = g_rowptr[node + 1];

    float m = -3.402823466e38f;   // -FLT_MAX
    float denom = 0.f;
    float4 acc = make_float4(0.f, 0.f, 0.f, 0.f);

    const float4* xlp = (const float4*)xl;
    int j = beg - 1;              // j == beg-1 encodes the self-loop
    float4 v = xlp[(size_t)node * 32 + lane];

    while (true) {
        // prefetch next edge
        int jn = j + 1;
        bool more = jn < end;
        int nsrc = 0;
        float4 nv = make_float4(0.f, 0.f, 0.f, 0.f);
        if (more) {
            nsrc = g_csrc[jn];
            nv = xlp[(size_t)nsrc * 32 + lane];
        }

        // leaky_relu(xl[src] + xr[dst]) dotted with att
        float tx = v.x + xrv.x; tx = tx > 0.f ? tx : 0.2f * tx;
        float ty = v.y + xrv.y; ty = ty > 0.f ? ty : 0.2f * ty;
        float tz = v.z + xrv.z; tz = tz > 0.f ? tz : 0.2f * tz;
        float tw = v.w + xrv.w; tw = tw > 0.f ? tw : 0.2f * tw;
        float part = attv.x * tx + attv.y * ty + attv.z * tz + attv.w * tw;
        part += __shfl_xor_sync(0xffffffffu, part, 1);
        part += __shfl_xor_sync(0xffffffffu, part, 2);
        part += __shfl_xor_sync(0xffffffffu, part, 4);
        if (FULLWARP) {
            part += __shfl_xor_sync(0xffffffffu, part, 8);
            part += __shfl_xor_sync(0xffffffffu, part, 16);
        }

        // online softmax update
        float nm = fmaxf(m, part);
        float sc = __expf(m - nm);
        float p  = __expf(part - nm);
        denom = denom * sc + p;
        acc.x = fmaf(p, v.x, acc.x * sc);
        acc.y = fmaf(p, v.y, acc.y * sc);
        acc.z = fmaf(p, v.z, acc.z * sc);
        acc.w = fmaf(p, v.w, acc.w * sc);
        m = nm;

        if (!more) break;
        j = jn;
        v = nv;
        (void)nsrc;
    }

    float inv = 1.f / denom;
    float4 bv = *(const float4*)(bias + (lane << 2));
    float ox = fmaf(acc.x, inv, bv.x);
    float oy = fmaf(acc.y, inv, bv.y);
    float oz = fmaf(acc.z, inv, bv.z);
    float ow = fmaf(acc.w, inv, bv.w);
    if (DOELU) {
        ox = ox > 0.f ? ox : __expf(ox) - 1.f;
        oy = oy > 0.f ? oy : __expf(oy) - 1.f;
        oz = oz > 0.f ? oz : __expf(oz) - 1.f;
        ow = ow > 0.f ? ow : __expf(ow) - 1.f;
    }
    *(float4*)(out + (size_t)node * 128 + (lane << 2)) = make_float4(ox, oy, oz, ow);
}

// ---------------- host launcher ----------------
extern "C" void kernel_launch(void* const* d_in, const int* in_sizes, int n_in,
                              void* d_out, int out_size)
{
    const float* x     = (const float*)d_in[0];
    const int*   ei    = (const int*)  d_in[1];
    const float* W1l   = (const float*)d_in[2];
    const float* b1l   = (const float*)d_in[3];
    const float* W1r   = (const float*)d_in[4];
    const float* b1r   = (const float*)d_in[5];
    const float* att1  = (const float*)d_in[6];
    const float* bias1 = (const float*)d_in[7];
    const float* W2l   = (const float*)d_in[8];
    const float* b2l   = (const float*)d_in[9];
    const float* W2r   = (const float*)d_in[10];
    const float* b2r   = (const float*)d_in[11];
    const float* att2  = (const float*)d_in[12];
    const float* bias2 = (const float*)d_in[13];

    int N = in_sizes[0] / 128;
    int E = in_sizes[1] / 2;

    void *p_xl, *p_xr, *p_h;
    cudaGetSymbolAddress(&p_xl, g_xl);
    cudaGetSymbolAddress(&p_xr, g_xr);
    cudaGetSymbolAddress(&p_h,  g_h);
    float* xl = (float*)p_xl;
    float* xr = (float*)p_xr;
    float* h  = (float*)p_h;

    const int TB = 256;

    // CSR build (dst-sorted adjacency for segment softmax without atomics)
    k_zero_counts<<<(N + TB - 1) / TB, TB>>>(N);
    k_hist<<<(E + TB - 1) / TB, TB>>>(ei, E);
    k_scan<<<1, 1024>>>(N);
    k_scatter<<<(E + TB - 1) / TB, TB>>>(ei, E);

    int gblocks = (N + 63) / 64;
    int ablocks = (N * 32 + TB - 1) / TB;

    // Layer 1
    k_gemm128<<<gblocks, TB>>>(x, W1l, b1l, xl, N);
    k_gemm128<<<gblocks, TB>>>(x, W1r, b1r, xr, N);
    k_agg<false, true><<<ablocks, TB>>>(xl, xr, att1, bias1, h, N);

    // Layer 2 (reuse xl/xr scratch)
    k_gemm128<<<gblocks, TB>>>(h, W2l, b2l, xl, N);
    k_gemm128<<<gblocks, TB>>>(h, W2r, b2r, xr, N);
    k_agg<true, false><<<ablocks, TB>>>(xl, xr, att2, bias2, (float*)d_out, N);
}

// round 2
// speedup vs baseline: 1.2436x; 1.2436x over previous
#include <cuda_runtime.h>
#include <math.h>

#define NMAX 50176
#define EMAX 800000

typedef unsigned long long u64;

// ---- device scratch (no runtime allocation allowed) ----
__device__ float g_xl[NMAX * 128];
__device__ float g_xr[NMAX * 128];
__device__ float g_h [NMAX * 128];
__device__ int   g_counts[NMAX];
__device__ int   g_rowptr[NMAX + 1];
__device__ int   g_cursor[NMAX];
__device__ int   g_csrc  [EMAX];

// ---- packed fp32x2 helpers (SASS FFMA2: 2x fp32 FMA throughput, IEEE exact) ----
__device__ __forceinline__ u64 pack2(float x, float y) {
    u64 r; asm("mov.b64 %0, {%1, %2};" : "=l"(r) : "f"(x), "f"(y)); return r;
}
__device__ __forceinline__ u64 fma2(u64 a, u64 b, u64 c) {
    u64 d; asm("fma.rn.f32x2 %0, %1, %2, %3;" : "=l"(d) : "l"(a), "l"(b), "l"(c)); return d;
}
__device__ __forceinline__ void unpack2(u64 v, float& x, float& y) {
    asm("mov.b64 {%0, %1}, %2;" : "=f"(x), "=f"(y) : "l"(v));
}

// ---------------- CSR build ----------------
__global__ void k_zero_counts(int n) {
    int i = blockIdx.x * blockDim.x + threadIdx.x;
    if (i < n) g_counts[i] = 0;
}

__global__ void k_hist(const int* __restrict__ ei, int E) {
    int e = blockIdx.x * blockDim.x + threadIdx.x;
    if (e < E) atomicAdd(&g_counts[ei[E + e]], 1);
}

__global__ void k_scan(int n) {
    __shared__ int part[1024];
    int tid = threadIdx.x;
    int chunk = (n + 1023) >> 10;
    int s0 = tid * chunk;
    int s1 = min(s0 + chunk, n);
    int s = 0;
    for (int i = s0; i < s1; i++) s += g_counts[i];
    part[tid] = s;
    __syncthreads();
    for (int off = 1; off < 1024; off <<= 1) {
        int v = (tid >= off) ? part[tid - off] : 0;
        __syncthreads();
        part[tid] += v;
        __syncthreads();
    }
    int base = (tid == 0) ? 0 : part[tid - 1];
    for (int i = s0; i < s1; i++) {
        g_rowptr[i] = base;
        g_cursor[i] = base;
        base += g_counts[i];
    }
    if (s1 == n) g_rowptr[n] = base;
}

__global__ void k_scatter(const int* __restrict__ ei, int E) {
    int e = blockIdx.x * blockDim.x + threadIdx.x;
    if (e < E) {
        int d = ei[E + e];
        int pos = atomicAdd(&g_cursor[d], 1);
        g_csrc[pos] = ei[e];
    }
}

// ---------------- Fused dual GEMM: C{l,r}[M,128] = A[M,128] @ W{l,r}[128,128] + b ----
// 128x128 tile, BK=16, 256 threads, 8x8 per thread via packed FFMA2.
// blockIdx.y selects (Wl,bl,Cl) vs (Wr,br,Cr).
__global__ __launch_bounds__(256, 2) void k_gemm2(
    const float* __restrict__ A,
    const float* __restrict__ Wl, const float* __restrict__ bl, float* __restrict__ Cl,
    const float* __restrict__ Wr, const float* __restrict__ br, float* __restrict__ Cr,
    int M)
{
    const float* W = blockIdx.y ? Wr : Wl;
    const float* bias = blockIdx.y ? br : bl;
    float* C = blockIdx.y ? Cr : Cl;

    __shared__ float As[16][132];   // k-major, padded pitch (16B-aligned rows)
    __shared__ float Ws[16][128];

    int tid = threadIdx.x;
    int row0 = blockIdx.x << 7;

    int ty8 = (tid >> 4) << 3;      // m offset 0..120
    int tx8 = (tid & 15) << 3;      // n offset 0..120

    // A tile loader: 512 float4 / 256 threads = 2 each (transposed store)
    int am0 = tid >> 2;             // 0..63
    int ak  = (tid & 3) << 2;       // 0,4,8,12
    // W tile loader
    int wk0 = tid >> 5;             // 0..7
    int wn  = (tid & 31) << 2;      // 0..124

    u64 acc[8][4];
#pragma unroll
    for (int i = 0; i < 8; i++)
#pragma unroll
        for (int j = 0; j < 4; j++) acc[i][j] = 0ULL;

    float4 av0, av1, wv0, wv1;

    // prefetch k-tile 0
    {
        int gm0 = row0 + am0, gm1 = row0 + am0 + 64;
        av0 = (gm0 < M) ? *(const float4*)(A + (size_t)gm0 * 128 + ak) : make_float4(0,0,0,0);
        av1 = (gm1 < M) ? *(const float4*)(A + (size_t)gm1 * 128 + ak) : make_float4(0,0,0,0);
        wv0 = *(const float4*)(W + (size_t)wk0 * 128 + wn);
        wv1 = *(const float4*)(W + (size_t)(wk0 + 8) * 128 + wn);
    }

#pragma unroll 1
    for (int t = 0; t < 8; ++t) {
        // stage tile t
        As[ak + 0][am0] = av0.x; As[ak + 1][am0] = av0.y;
        As[ak + 2][am0] = av0.z; As[ak + 3][am0] = av0.w;
        As[ak + 0][am0 + 64] = av1.x; As[ak + 1][am0 + 64] = av1.y;
        As[ak + 2][am0 + 64] = av1.z; As[ak + 3][am0 + 64] = av1.w;
        *(float4*)&Ws[wk0][wn]     = wv0;
        *(float4*)&Ws[wk0 + 8][wn] = wv1;
        __syncthreads();

        // prefetch tile t+1
        if (t < 7) {
            int k0 = (t + 1) << 4;
            int gm0 = row0 + am0, gm1 = row0 + am0 + 64;
            av0 = (gm0 < M) ? *(const float4*)(A + (size_t)gm0 * 128 + k0 + ak) : make_float4(0,0,0,0);
            av1 = (gm1 < M) ? *(const float4*)(A + (size_t)gm1 * 128 + k0 + ak) : make_float4(0,0,0,0);
            wv0 = *(const float4*)(W + (size_t)(k0 + wk0) * 128 + wn);
            wv1 = *(const float4*)(W + (size_t)(k0 + wk0 + 8) * 128 + wn);
        }

#pragma unroll
        for (int k = 0; k < 16; ++k) {
            float4 aA = *(const float4*)&As[k][ty8];
            float4 aB = *(const float4*)&As[k][ty8 + 4];
            ulonglong2 b0 = *(const ulonglong2*)&Ws[k][tx8];
            ulonglong2 b1 = *(const ulonglong2*)&Ws[k][tx8 + 4];
            float am[8] = {aA.x, aA.y, aA.z, aA.w, aB.x, aB.y, aB.z, aB.w};
#pragma unroll
            for (int i = 0; i < 8; i++) {
                u64 aa = pack2(am[i], am[i]);
                acc[i][0] = fma2(aa, b0.x, acc[i][0]);
                acc[i][1] = fma2(aa, b0.y, acc[i][1]);
                acc[i][2] = fma2(aa, b1.x, acc[i][2]);
                acc[i][3] = fma2(aa, b1.y, acc[i][3]);
            }
        }
        __syncthreads();
    }

    float4 bv0 = *(const float4*)(bias + tx8);
    float4 bv1 = *(const float4*)(bias + tx8 + 4);
#pragma unroll
    for (int i = 0; i < 8; i++) {
        int gm = row0 + ty8 + i;
        if (gm < M) {
            float o[8];
            unpack2(acc[i][0], o[0], o[1]);
            unpack2(acc[i][1], o[2], o[3]);
            unpack2(acc[i][2], o[4], o[5]);
            unpack2(acc[i][3], o[6], o[7]);
            float4 r0 = make_float4(o[0] + bv0.x, o[1] + bv0.y, o[2] + bv0.z, o[3] + bv0.w);
            float4 r1 = make_float4(o[4] + bv1.x, o[5] + bv1.y, o[6] + bv1.z, o[7] + bv1.w);
            *(float4*)(C + (size_t)gm * 128 + tx8)     = r0;
            *(float4*)(C + (size_t)gm * 128 + tx8 + 4) = r1;
        }
    }
}

// ---------------- GATv2 aggregation: one warp per destination node ----------------
template<bool FULLWARP, bool DOELU>
__global__ __launch_bounds__(256) void k_agg(
    const float* __restrict__ xl, const float* __restrict__ xr,
    const float* __restrict__ att, const float* __restrict__ bias,
    float* __restrict__ out, int n)
{
    int gw = (blockIdx.x * blockDim.x + threadIdx.x) >> 5;
    if (gw >= n) return;
    int lane = threadIdx.x & 31;
    int node = gw;

    float4 attv = *(const float4*)(att + (lane << 2));
    float4 xrv  = *(const float4*)(xr + (size_t)node * 128 + (lane << 2));

    int beg = g_rowptr[node];
    int end = g_rowptr[node + 1];

    float m = -3.402823466e38f;
    float denom = 0.f;
    float4 acc = make_float4(0.f, 0.f, 0.f, 0.f);

    const float4* xlp = (const float4*)xl;
    int j = beg - 1;              // beg-1 encodes the self-loop
    float4 v = xlp[(size_t)node * 32 + lane];

    while (true) {
        int jn = j + 1;
        bool more = jn < end;
        float4 nv = make_float4(0.f, 0.f, 0.f, 0.f);
        if (more) {
            int nsrc = g_csrc[jn];
            nv = xlp[(size_t)nsrc * 32 + lane];
        }

        float tx = v.x + xrv.x; tx = tx > 0.f ? tx : 0.2f * tx;
        float ty = v.y + xrv.y; ty = ty > 0.f ? ty : 0.2f * ty;
        float tz = v.z + xrv.z; tz = tz > 0.f ? tz : 0.2f * tz;
        float tw = v.w + xrv.w; tw = tw > 0.f ? tw : 0.2f * tw;
        float part = attv.x * tx + attv.y * ty + attv.z * tz + attv.w * tw;
        part += __shfl_xor_sync(0xffffffffu, part, 1);
        part += __shfl_xor_sync(0xffffffffu, part, 2);
        part += __shfl_xor_sync(0xffffffffu, part, 4);
        if (FULLWARP) {
            part += __shfl_xor_sync(0xffffffffu, part, 8);
            part += __shfl_xor_sync(0xffffffffu, part, 16);
        }

        float nm = fmaxf(m, part);
        float sc = __expf(m - nm);
        float p  = __expf(part - nm);
        denom = denom * sc + p;
        acc.x = fmaf(p, v.x, acc.x * sc);
        acc.y = fmaf(p, v.y, acc.y * sc);
        acc.z = fmaf(p, v.z, acc.z * sc);
        acc.w = fmaf(p, v.w, acc.w * sc);
        m = nm;

        if (!more) break;
        j = jn;
        v = nv;
    }

    float inv = 1.f / denom;
    float4 bv = *(const float4*)(bias + (lane << 2));
    float ox = fmaf(acc.x, inv, bv.x);
    float oy = fmaf(acc.y, inv, bv.y);
    float oz = fmaf(acc.z, inv, bv.z);
    float ow = fmaf(acc.w, inv, bv.w);
    if (DOELU) {
        ox = ox > 0.f ? ox : __expf(ox) - 1.f;
        oy = oy > 0.f ? oy : __expf(oy) - 1.f;
        oz = oz > 0.f ? oz : __expf(oz) - 1.f;
        ow = ow > 0.f ? ow : __expf(ow) - 1.f;
    }
    *(float4*)(out + (size_t)node * 128 + (lane << 2)) = make_float4(ox, oy, oz, ow);
}

// ---------------- host launcher ----------------
extern "C" void kernel_launch(void* const* d_in, const int* in_sizes, int n_in,
                              void* d_out, int out_size)
{
    const float* x     = (const float*)d_in[0];
    const int*   ei    = (const int*)  d_in[1];
    const float* W1l   = (const float*)d_in[2];
    const float* b1l   = (const float*)d_in[3];
    const float* W1r   = (const float*)d_in[4];
    const float* b1r   = (const float*)d_in[5];
    const float* att1  = (const float*)d_in[6];
    const float* bias1 = (const float*)d_in[7];
    const float* W2l   = (const float*)d_in[8];
    const float* b2l   = (const float*)d_in[9];
    const float* W2r   = (const float*)d_in[10];
    const float* b2r   = (const float*)d_in[11];
    const float* att2  = (const float*)d_in[12];
    const float* bias2 = (const float*)d_in[13];

    int N = in_sizes[0] / 128;
    int E = in_sizes[1] / 2;

    void *p_xl, *p_xr, *p_h;
    cudaGetSymbolAddress(&p_xl, g_xl);
    cudaGetSymbolAddress(&p_xr, g_xr);
    cudaGetSymbolAddress(&p_h,  g_h);
    float* xl = (float*)p_xl;
    float* xr = (float*)p_xr;
    float* h  = (float*)p_h;

    const int TB = 256;

    // CSR build
    k_zero_counts<<<(N + TB - 1) / TB, TB>>>(N);
    k_hist<<<(E + TB - 1) / TB, TB>>>(ei, E);
    k_scan<<<1, 1024>>>(N);
    k_scatter<<<(E + TB - 1) / TB, TB>>>(ei, E);

    dim3 ggrid((N + 127) / 128, 2);
    int ablocks = (N * 32 + TB - 1) / TB;

    // Layer 1
    k_gemm2<<<ggrid, TB>>>(x, W1l, b1l, xl, W1r, b1r, xr, N);
    k_agg<false, true><<<ablocks, TB>>>(xl, xr, att1, bias1, h, N);

    // Layer 2
    k_gemm2<<<ggrid, TB>>>(h, W2l, b2l, xl, W2r, b2r, xr, N);
    k_agg<true, false><<<ablocks, TB>>>(xl, xr, att2, bias2, (float*)d_out, N);
}

// round 3
// speedup vs baseline: 1.2591x; 1.0125x over previous
#include <cuda_runtime.h>
#include <math.h>

#define NMAX 50176
#define EMAX 800000

typedef unsigned long long u64;

// ---- device scratch (no runtime allocation allowed) ----
__device__ float g_xl[NMAX * 128];
__device__ float g_xr[NMAX * 128];
__device__ float g_h [NMAX * 128];
__device__ int   g_counts[NMAX];
__device__ int   g_rowptr[NMAX + 1];
__device__ int   g_cursor[NMAX];
__device__ int   g_csrc  [EMAX];

// ---- packed fp32x2 helpers (SASS FFMA2: 2x fp32 FMA throughput, IEEE exact) ----
__device__ __forceinline__ u64 pack2(float x, float y) {
    u64 r; asm("mov.b64 %0, {%1, %2};" : "=l"(r) : "f"(x), "f"(y)); return r;
}
__device__ __forceinline__ u64 fma2(u64 a, u64 b, u64 c) {
    u64 d; asm("fma.rn.f32x2 %0, %1, %2, %3;" : "=l"(d) : "l"(a), "l"(b), "l"(c)); return d;
}
__device__ __forceinline__ void unpack2(u64 v, float& x, float& y) {
    asm("mov.b64 {%0, %1}, %2;" : "=f"(x), "=f"(y) : "l"(v));
}

// ---------------- CSR build ----------------
__global__ void k_zero_counts(int n) {
    int i = blockIdx.x * blockDim.x + threadIdx.x;
    if (i < n) g_counts[i] = 0;
}

__global__ void k_hist(const int* __restrict__ ei, int E) {
    int e = blockIdx.x * blockDim.x + threadIdx.x;
    if (e < E) atomicAdd(&g_counts[ei[E + e]], 1);
}

__global__ void k_scan(int n) {
    __shared__ int part[1024];
    int tid = threadIdx.x;
    int chunk = (n + 1023) >> 10;
    int s0 = tid * chunk;
    int s1 = min(s0 + chunk, n);
    int s = 0;
    for (int i = s0; i < s1; i++) s += g_counts[i];
    part[tid] = s;
    __syncthreads();
    for (int off = 1; off < 1024; off <<= 1) {
        int v = (tid >= off) ? part[tid - off] : 0;
        __syncthreads();
        part[tid] += v;
        __syncthreads();
    }
    int base = (tid == 0) ? 0 : part[tid - 1];
    for (int i = s0; i < s1; i++) {
        g_rowptr[i] = base;
        g_cursor[i] = base;
        base += g_counts[i];
    }
    if (s1 == n) g_rowptr[n] = base;
}

__global__ void k_scatter(const int* __restrict__ ei, int E) {
    int e = blockIdx.x * blockDim.x + threadIdx.x;
    if (e < E) {
        int d = ei[E + e];
        int pos = atomicAdd(&g_cursor[d], 1);
        g_csrc[pos] = ei[e];
    }
}

// ---------------- Fused dual GEMM: C{l,r}[M,128] = A[M,128] @ W{l,r}[128,128] + b ----
__global__ __launch_bounds__(256, 2) void k_gemm2(
    const float* __restrict__ A,
    const float* __restrict__ Wl, const float* __restrict__ bl, float* __restrict__ Cl,
    const float* __restrict__ Wr, const float* __restrict__ br, float* __restrict__ Cr,
    int M)
{
    const float* W = blockIdx.y ? Wr : Wl;
    const float* bias = blockIdx.y ? br : bl;
    float* C = blockIdx.y ? Cr : Cl;

    __shared__ float As[16][132];   // k-major, padded pitch
    __shared__ float Ws[16][128];

    int tid = threadIdx.x;
    int row0 = blockIdx.x << 7;

    int ty8 = (tid >> 4) << 3;      // m offset 0..120
    int tx8 = (tid & 15) << 3;      // n offset 0..120

    int am0 = tid >> 2;             // 0..63
    int ak  = (tid & 3) << 2;       // 0,4,8,12
    int wk0 = tid >> 5;             // 0..7
    int wn  = (tid & 31) << 2;      // 0..124

    u64 acc[8][4];
#pragma unroll
    for (int i = 0; i < 8; i++)
#pragma unroll
        for (int j = 0; j < 4; j++) acc[i][j] = 0ULL;

    float4 av0, av1, wv0, wv1;
    {
        int gm0 = row0 + am0, gm1 = row0 + am0 + 64;
        av0 = (gm0 < M) ? *(const float4*)(A + (size_t)gm0 * 128 + ak) : make_float4(0,0,0,0);
        av1 = (gm1 < M) ? *(const float4*)(A + (size_t)gm1 * 128 + ak) : make_float4(0,0,0,0);
        wv0 = *(const float4*)(W + (size_t)wk0 * 128 + wn);
        wv1 = *(const float4*)(W + (size_t)(wk0 + 8) * 128 + wn);
    }

#pragma unroll 1
    for (int t = 0; t < 8; ++t) {
        As[ak + 0][am0] = av0.x; As[ak + 1][am0] = av0.y;
        As[ak + 2][am0] = av0.z; As[ak + 3][am0] = av0.w;
        As[ak + 0][am0 + 64] = av1.x; As[ak + 1][am0 + 64] = av1.y;
        As[ak + 2][am0 + 64] = av1.z; As[ak + 3][am0 + 64] = av1.w;
        *(float4*)&Ws[wk0][wn]     = wv0;
        *(float4*)&Ws[wk0 + 8][wn] = wv1;
        __syncthreads();

        if (t < 7) {
            int k0 = (t + 1) << 4;
            int gm0 = row0 + am0, gm1 = row0 + am0 + 64;
            av0 = (gm0 < M) ? *(const float4*)(A + (size_t)gm0 * 128 + k0 + ak) : make_float4(0,0,0,0);
            av1 = (gm1 < M) ? *(const float4*)(A + (size_t)gm1 * 128 + k0 + ak) : make_float4(0,0,0,0);
            wv0 = *(const float4*)(W + (size_t)(k0 + wk0) * 128 + wn);
            wv1 = *(const float4*)(W + (size_t)(k0 + wk0 + 8) * 128 + wn);
        }

#pragma unroll
        for (int k = 0; k < 16; ++k) {
            float4 aA = *(const float4*)&As[k][ty8];
            float4 aB = *(const float4*)&As[k][ty8 + 4];
            ulonglong2 b0 = *(const ulonglong2*)&Ws[k][tx8];
            ulonglong2 b1 = *(const ulonglong2*)&Ws[k][tx8 + 4];
            float am[8] = {aA.x, aA.y, aA.z, aA.w, aB.x, aB.y, aB.z, aB.w};
#pragma unroll
            for (int i = 0; i < 8; i++) {
                u64 aa = pack2(am[i], am[i]);
                acc[i][0] = fma2(aa, b0.x, acc[i][0]);
                acc[i][1] = fma2(aa, b0.y, acc[i][1]);
                acc[i][2] = fma2(aa, b1.x, acc[i][2]);
                acc[i][3] = fma2(aa, b1.y, acc[i][3]);
            }
        }
        __syncthreads();
    }

    float4 bv0 = *(const float4*)(bias + tx8);
    float4 bv1 = *(const float4*)(bias + tx8 + 4);
#pragma unroll
    for (int i = 0; i < 8; i++) {
        int gm = row0 + ty8 + i;
        if (gm < M) {
            float o[8];
            unpack2(acc[i][0], o[0], o[1]);
            unpack2(acc[i][1], o[2], o[3]);
            unpack2(acc[i][2], o[4], o[5]);
            unpack2(acc[i][3], o[6], o[7]);
            float4 r0 = make_float4(o[0] + bv0.x, o[1] + bv0.y, o[2] + bv0.z, o[3] + bv0.w);
            float4 r1 = make_float4(o[4] + bv1.x, o[5] + bv1.y, o[6] + bv1.z, o[7] + bv1.w);
            *(float4*)(C + (size_t)gm * 128 + tx8)     = r0;
            *(float4*)(C + (size_t)gm * 128 + tx8 + 4) = r1;
        }
    }
}

// ---------------- GATv2 aggregation: one warp per destination node ----------------
// Depth-2 software pipeline on the neighbor gather (MLP=2 against ~250cyc L2 latency).
template<bool FULLWARP, bool DOELU>
__global__ __launch_bounds__(256) void k_agg(
    const float* __restrict__ xl, const float* __restrict__ xr,
    const float* __restrict__ att, const float* __restrict__ bias,
    float* __restrict__ out, int n)
{
    int gw = (blockIdx.x * blockDim.x + threadIdx.x) >> 5;
    if (gw >= n) return;
    int lane = threadIdx.x & 31;
    int node = gw;

    float4 attv = *(const float4*)(att + (lane << 2));
    float4 xrv  = *(const float4*)(xr + (size_t)node * 128 + (lane << 2));

    int beg = g_rowptr[node];
    int cnt = g_rowptr[node + 1] - beg;   // CSR neighbors (self-loop extra)

    float m = -3.402823466e38f;
    float denom = 0.f;
    float4 acc = make_float4(0.f, 0.f, 0.f, 0.f);

    const float4* xlp = (const float4*)xl;

    // pipeline: slot 0 = self-loop, slots 1..cnt = CSR edges
    float4 v0 = xlp[(size_t)node * 32 + lane];
    float4 v1 = make_float4(0.f, 0.f, 0.f, 0.f);
    if (cnt > 0) v1 = xlp[(size_t)g_csrc[beg] * 32 + lane];

    int i = 0;
    while (true) {
        // prefetch slot i+2
        float4 v2 = make_float4(0.f, 0.f, 0.f, 0.f);
        if (i + 2 <= cnt) v2 = xlp[(size_t)g_csrc[beg + i + 1] * 32 + lane];

        // process slot i (v0)
        float tx = v0.x + xrv.x; tx = tx > 0.f ? tx : 0.2f * tx;
        float ty = v0.y + xrv.y; ty = ty > 0.f ? ty : 0.2f * ty;
        float tz = v0.z + xrv.z; tz = tz > 0.f ? tz : 0.2f * tz;
        float tw = v0.w + xrv.w; tw = tw > 0.f ? tw : 0.2f * tw;
        float part = attv.x * tx + attv.y * ty + attv.z * tz + attv.w * tw;
        part += __shfl_xor_sync(0xffffffffu, part, 1);
        part += __shfl_xor_sync(0xffffffffu, part, 2);
        part += __shfl_xor_sync(0xffffffffu, part, 4);
        if (FULLWARP) {
            part += __shfl_xor_sync(0xffffffffu, part, 8);
            part += __shfl_xor_sync(0xffffffffu, part, 16);
        }

        float nm = fmaxf(m, part);
        float sc = __expf(m - nm);
        float p  = __expf(part - nm);
        denom = denom * sc + p;
        acc.x = fmaf(p, v0.x, acc.x * sc);
        acc.y = fmaf(p, v0.y, acc.y * sc);
        acc.z = fmaf(p, v0.z, acc.z * sc);
        acc.w = fmaf(p, v0.w, acc.w * sc);
        m = nm;

        if (++i > cnt) break;
        v0 = v1;
        v1 = v2;
    }

    float inv = 1.f / denom;
    float4 bv = *(const float4*)(bias + (lane << 2));
    float ox = fmaf(acc.x, inv, bv.x);
    float oy = fmaf(acc.y, inv, bv.y);
    float oz = fmaf(acc.z, inv, bv.z);
    float ow = fmaf(acc.w, inv, bv.w);
    if (DOELU) {
        ox = ox > 0.f ? ox : __expf(ox) - 1.f;
        oy = oy > 0.f ? oy : __expf(oy) - 1.f;
        oz = oz > 0.f ? oz : __expf(oz) - 1.f;
        ow = ow > 0.f ? ow : __expf(ow) - 1.f;
    }
    *(float4*)(out + (size_t)node * 128 + (lane << 2)) = make_float4(ox, oy, oz, ow);
}

// ---------------- host launcher ----------------
extern "C" void kernel_launch(void* const* d_in, const int* in_sizes, int n_in,
                              void* d_out, int out_size)
{
    const float* x     = (const float*)d_in[0];
    const int*   ei    = (const int*)  d_in[1];
    const float* W1l   = (const float*)d_in[2];
    const float* b1l   = (const float*)d_in[3];
    const float* W1r   = (const float*)d_in[4];
    const float* b1r   = (const float*)d_in[5];
    const float* att1  = (const float*)d_in[6];
    const float* bias1 = (const float*)d_in[7];
    const float* W2l   = (const float*)d_in[8];
    const float* b2l   = (const float*)d_in[9];
    const float* W2r   = (const float*)d_in[10];
    const float* b2r   = (const float*)d_in[11];
    const float* att2  = (const float*)d_in[12];
    const float* bias2 = (const float*)d_in[13];

    int N = in_sizes[0] / 128;
    int E = in_sizes[1] / 2;

    void *p_xl, *p_xr, *p_h;
    cudaGetSymbolAddress(&p_xl, g_xl);
    cudaGetSymbolAddress(&p_xr, g_xr);
    cudaGetSymbolAddress(&p_h,  g_h);
    float* xl = (float*)p_xl;
    float* xr = (float*)p_xr;
    float* h  = (float*)p_h;

    // lazily-created side stream + events (host-only resources; enqueued work
    // is identical on every call)
    static cudaStream_t s_csr = nullptr;
    static cudaEvent_t ev_fork = nullptr, ev_join = nullptr;
    if (s_csr == nullptr) {
        cudaStreamCreateWithFlags(&s_csr, cudaStreamNonBlocking);
        cudaEventCreateWithFlags(&ev_fork, cudaEventDisableTiming);
        cudaEventCreateWithFlags(&ev_join, cudaEventDisableTiming);
    }

    const int TB = 256;
    dim3 ggrid((N + 127) / 128, 2);
    int ablocks = (N * 32 + TB - 1) / TB;

    // Fork: CSR build runs on side stream, concurrent with layer-1 GEMMs.
    cudaEventRecord(ev_fork, 0);
    cudaStreamWaitEvent(s_csr, ev_fork, 0);
    k_zero_counts<<<(N + TB - 1) / TB, TB, 0, s_csr>>>(N);
    k_hist<<<(E + TB - 1) / TB, TB, 0, s_csr>>>(ei, E);
    k_scan<<<1, 1024, 0, s_csr>>>(N);
    k_scatter<<<(E + TB - 1) / TB, TB, 0, s_csr>>>(ei, E);
    cudaEventRecord(ev_join, s_csr);

    // Layer-1 GEMMs on main stream (independent of CSR)
    k_gemm2<<<ggrid, TB>>>(x, W1l, b1l, xl, W1r, b1r, xr, N);

    // Join: aggregation needs both CSR and GEMM outputs
    cudaStreamWaitEvent(0, ev_join, 0);
    k_agg<false, true><<<ablocks, TB>>>(xl, xr, att1, bias1, h, N);

    // Layer 2
    k_gemm2<<<ggrid, TB>>>(h, W2l, b2l, xl, W2r, b2r, xr, N);
    k_agg<true, false><<<ablocks, TB>>>(xl, xr, att2, bias2, (float*)d_out, N);
}

// round 5
// speedup vs baseline: 1.3913x; 1.1050x over previous
#include <cuda_runtime.h>
#include <cuda_bf16.h>
#include <math.h>
#include <stdint.h>

#define NMAX 50176
#define EMAX 800000

typedef unsigned long long u64;

// ---- device scratch (no runtime allocation allowed) ----
__device__ float g_xl[NMAX * 128];
__device__ float g_xr[NMAX * 128];
__device__ float g_h [NMAX * 128];
__device__ int   g_counts[NMAX];
__device__ int   g_rowptr[NMAX + 1];
__device__ int   g_cursor[NMAX];
__device__ int   g_csrc  [EMAX];

// ---------------- CSR build ----------------
__global__ void k_zero_counts(int n) {
    int i = blockIdx.x * blockDim.x + threadIdx.x;
    if (i < n) g_counts[i] = 0;
}

__global__ void k_hist(const int* __restrict__ ei, int E) {
    int e = blockIdx.x * blockDim.x + threadIdx.x;
    if (e < E) atomicAdd(&g_counts[ei[E + e]], 1);
}

__global__ void k_scan(int n) {
    __shared__ int part[1024];
    int tid = threadIdx.x;
    int chunk = (n + 1023) >> 10;
    int s0 = tid * chunk;
    int s1 = min(s0 + chunk, n);
    int s = 0;
    for (int i = s0; i < s1; i++) s += g_counts[i];
    part[tid] = s;
    __syncthreads();
    for (int off = 1; off < 1024; off <<= 1) {
        int v = (tid >= off) ? part[tid - off] : 0;
        __syncthreads();
        part[tid] += v;
        __syncthreads();
    }
    int base = (tid == 0) ? 0 : part[tid - 1];
    for (int i = s0; i < s1; i++) {
        g_rowptr[i] = base;
        g_cursor[i] = base;
        base += g_counts[i];
    }
    if (s1 == n) g_rowptr[n] = base;
}

__global__ void k_scatter(const int* __restrict__ ei, int E) {
    int e = blockIdx.x * blockDim.x + threadIdx.x;
    if (e < E) {
        int d = ei[E + e];
        int pos = atomicAdd(&g_cursor[d], 1);
        g_csrc[pos] = ei[e];
    }
}

// =================== split-bf16 HMMA GEMM ===================
// C{l,r}[M,128] = A[M,128] @ W{l,r}[128,128] + b, computed as
// Ah*Bh + Ah*Bl + Al*Bh with fp32 accumulation (mma.sync m16n8k16 bf16).
// One CTA: 128x128x128 tile. 8 warps = 4(M) x 2(N). In-kernel fp32->split-bf16
// conversion into smem (A row-major [m][k], B as W^T row-major [n][k]).

#define PITCH 136                      // bf16 elems per smem row (272B: conflict-free ldmatrix)
#define AS_H 0
#define AS_L (128 * PITCH)
#define BS_H (2 * 128 * PITCH)
#define BS_L (3 * 128 * PITCH)
#define GEMM_SMEM_BYTES (4 * 128 * PITCH * 2)

__device__ __forceinline__ uint32_t smem_u32(const void* p) {
    uint32_t a;
    asm("{ .reg .u64 t; cvta.to.shared.u64 t, %1; cvt.u32.u64 %0, t; }"
        : "=r"(a) : "l"(p));
    return a;
}

__device__ __forceinline__ void ldsm4(uint32_t& r0, uint32_t& r1, uint32_t& r2,
                                      uint32_t& r3, uint32_t addr) {
    asm volatile("ldmatrix.sync.aligned.m8n8.x4.shared.b16 {%0,%1,%2,%3}, [%4];"
        : "=r"(r0), "=r"(r1), "=r"(r2), "=r"(r3) : "r"(addr));
}

__device__ __forceinline__ void mma16816(float* c, uint32_t a0, uint32_t a1,
                                         uint32_t a2, uint32_t a3,
                                         uint32_t b0, uint32_t b1) {
    asm volatile(
        "mma.sync.aligned.m16n8k16.row.col.f32.bf16.bf16.f32 "
        "{%0,%1,%2,%3}, {%4,%5,%6,%7}, {%8,%9}, {%0,%1,%2,%3};"
        : "+f"(c[0]), "+f"(c[1]), "+f"(c[2]), "+f"(c[3])
        : "r"(a0), "r"(a1), "r"(a2), "r"(a3), "r"(b0), "r"(b1));
}

__device__ __forceinline__ unsigned short bf_hi(float f) {
    return __bfloat16_as_ushort(__float2bfloat16(f));
}
__device__ __forceinline__ unsigned short bf_lo(float f, unsigned short hi) {
    float fh = __bfloat162float(__ushort_as_bfloat16(hi));
    return __bfloat16_as_ushort(__float2bfloat16(f - fh));
}

__global__ __launch_bounds__(256, 1) void k_gemm_mma(
    const float* __restrict__ A,
    const float* __restrict__ Wl, const float* __restrict__ bl, float* __restrict__ Cl,
    const float* __restrict__ Wr, const float* __restrict__ br, float* __restrict__ Cr,
    int M)
{
    extern __shared__ __align__(16) unsigned short sm[];
    const float* W = blockIdx.y ? Wr : Wl;
    const float* bias = blockIdx.y ? br : bl;
    float* C = blockIdx.y ? Cr : Cl;

    int tid = threadIdx.x;
    int row0 = blockIdx.x << 7;

    // ---- stage A: fp32 [128,128] -> split bf16 smem, row-major, pitch 136 ----
    {
        const float4* A4 = (const float4*)(A + (size_t)row0 * 128);
#pragma unroll
        for (int i = 0; i < 16; i++) {
            int idx = tid + (i << 8);       // float4 index, 0..4095
            int r = idx >> 5;               // row 0..127
            int c = (idx & 31) << 2;        // col 0..124
            float4 v = (row0 + r < M) ? A4[idx] : make_float4(0.f, 0.f, 0.f, 0.f);
            ushort4 h, l;
            h.x = bf_hi(v.x); l.x = bf_lo(v.x, h.x);
            h.y = bf_hi(v.y); l.y = bf_lo(v.y, h.y);
            h.z = bf_hi(v.z); l.z = bf_lo(v.z, h.z);
            h.w = bf_hi(v.w); l.w = bf_lo(v.w, h.w);
            *(ushort4*)&sm[AS_H + r * PITCH + c] = h;
            *(ushort4*)&sm[AS_L + r * PITCH + c] = l;
        }
    }
    // ---- stage B: W fp32 [k][n] -> B = W^T split bf16 smem [n][k] ----
    {
#pragma unroll
        for (int i = 0; i < 64; i++) {
            int idx = tid + (i << 8);       // 0..16383, coalesced over n
            int k = idx >> 7;
            int n = idx & 127;
            float w = W[idx];
            unsigned short h = bf_hi(w);
            sm[BS_H + n * PITCH + k] = h;
            sm[BS_L + n * PITCH + k] = bf_lo(w, h);
        }
    }
    __syncthreads();

    int wid = tid >> 5, lane = tid & 31;
    int wm = (wid >> 1) << 5;    // warp m offset: 0,32,64,96
    int wn = (wid & 1) << 6;     // warp n offset: 0,64

    float acc[2][8][4];
#pragma unroll
    for (int mt = 0; mt < 2; mt++)
#pragma unroll
        for (int nt = 0; nt < 8; nt++)
#pragma unroll
            for (int q = 0; q < 4; q++) acc[mt][nt][q] = 0.f;

    // ldmatrix per-lane addressing (element offsets)
    int a_row = lane & 15;
    int a_col = (lane >> 4) << 3;                      // 0 or 8
    int b_row = ((lane >> 4) << 3) + (lane & 7);       // n-row within 16
    int b_col = ((lane >> 3) & 1) << 3;                // 0 or 8

    uint32_t sb = smem_u32(sm);

    const int APASS[3] = {AS_H, AS_H, AS_L};
    const int BPASS[3] = {BS_H, BS_L, BS_H};

#pragma unroll
    for (int pass = 0; pass < 3; pass++) {
        uint32_t abase = sb + ((uint32_t)(APASS[pass] + (wm + a_row) * PITCH + a_col) << 1);
        uint32_t bbase = sb + ((uint32_t)(BPASS[pass] + (wn + b_row) * PITCH + b_col) << 1);
#pragma unroll
        for (int ks = 0; ks < 8; ks++) {
            int k0 = ks << 4;
            uint32_t af[2][4];
            ldsm4(af[0][0], af[0][1], af[0][2], af[0][3], abase + (k0 << 1));
            ldsm4(af[1][0], af[1][1], af[1][2], af[1][3],
                  abase + (k0 << 1) + (16 * PITCH << 1));
            uint32_t bf[4][4];
#pragma unroll
            for (int g = 0; g < 4; g++)
                ldsm4(bf[g][0], bf[g][1], bf[g][2], bf[g][3],
                      bbase + (k0 << 1) + ((g * 16 * PITCH) << 1));
#pragma unroll
            for (int mt = 0; mt < 2; mt++)
#pragma unroll
                for (int nt = 0; nt < 8; nt++) {
                    uint32_t b0 = bf[nt >> 1][(nt & 1) << 1];
                    uint32_t b1 = bf[nt >> 1][((nt & 1) << 1) + 1];
                    mma16816(acc[mt][nt], af[mt][0], af[mt][1], af[mt][2], af[mt][3], b0, b1);
                }
        }
    }

    // ---- epilogue: add bias, store fp32 ----
    int g = lane >> 2, tg = lane & 3;
#pragma unroll
    for (int mt = 0; mt < 2; mt++) {
        int rlo = row0 + wm + (mt << 4) + g;
        int rhi = rlo + 8;
#pragma unroll
        for (int nt = 0; nt < 8; nt++) {
            int col = wn + (nt << 3) + (tg << 1);
            float2 bv = *(const float2*)(bias + col);
            if (rlo < M) {
                float2 o = make_float2(acc[mt][nt][0] + bv.x, acc[mt][nt][1] + bv.y);
                *(float2*)(C + (size_t)rlo * 128 + col) = o;
            }
            if (rhi < M) {
                float2 o = make_float2(acc[mt][nt][2] + bv.x, acc[mt][nt][3] + bv.y);
                *(float2*)(C + (size_t)rhi * 128 + col) = o;
            }
        }
    }
}

// ---------------- GATv2 aggregation: one warp per destination node ----------------
template<bool FULLWARP, bool DOELU>
__global__ __launch_bounds__(256) void k_agg(
    const float* __restrict__ xl, const float* __restrict__ xr,
    const float* __restrict__ att, const float* __restrict__ bias,
    float* __restrict__ out, int n)
{
    int gw = (blockIdx.x * blockDim.x + threadIdx.x) >> 5;
    if (gw >= n) return;
    int lane = threadIdx.x & 31;
    int node = gw;

    float4 attv = *(const float4*)(att + (lane << 2));
    float4 xrv  = *(const float4*)(xr + (size_t)node * 128 + (lane << 2));

    int beg = g_rowptr[node];
    int cnt = g_rowptr[node + 1] - beg;

    float m = -3.402823466e38f;
    float denom = 0.f;
    float4 acc = make_float4(0.f, 0.f, 0.f, 0.f);

    const float4* xlp = (const float4*)xl;

    float4 v0 = xlp[(size_t)node * 32 + lane];
    float4 v1 = make_float4(0.f, 0.f, 0.f, 0.f);
    if (cnt > 0) v1 = xlp[(size_t)g_csrc[beg] * 32 + lane];

    int i = 0;
    while (true) {
        float4 v2 = make_float4(0.f, 0.f, 0.f, 0.f);
        if (i + 2 <= cnt) v2 = xlp[(size_t)g_csrc[beg + i + 1] * 32 + lane];

        float tx = v0.x + xrv.x; tx = tx > 0.f ? tx : 0.2f * tx;
        float ty = v0.y + xrv.y; ty = ty > 0.f ? ty : 0.2f * ty;
        float tz = v0.z + xrv.z; tz = tz > 0.f ? tz : 0.2f * tz;
        float tw = v0.w + xrv.w; tw = tw > 0.f ? tw : 0.2f * tw;
        float part = attv.x * tx + attv.y * ty + attv.z * tz + attv.w * tw;
        part += __shfl_xor_sync(0xffffffffu, part, 1);
        part += __shfl_xor_sync(0xffffffffu, part, 2);
        part += __shfl_xor_sync(0xffffffffu, part, 4);
        if (FULLWARP) {
            part += __shfl_xor_sync(0xffffffffu, part, 8);
            part += __shfl_xor_sync(0xffffffffu, part, 16);
        }

        float nm = fmaxf(m, part);
        float sc = __expf(m - nm);
        float p  = __expf(part - nm);
        denom = denom * sc + p;
        acc.x = fmaf(p, v0.x, acc.x * sc);
        acc.y = fmaf(p, v0.y, acc.y * sc);
        acc.z = fmaf(p, v0.z, acc.z * sc);
        acc.w = fmaf(p, v0.w, acc.w * sc);
        m = nm;

        if (++i > cnt) break;
        v0 = v1;
        v1 = v2;
    }

    float inv = 1.f / denom;
    float4 bv = *(const float4*)(bias + (lane << 2));
    float ox = fmaf(acc.x, inv, bv.x);
    float oy = fmaf(acc.y, inv, bv.y);
    float oz = fmaf(acc.z, inv, bv.z);
    float ow = fmaf(acc.w, inv, bv.w);
    if (DOELU) {
        ox = ox > 0.f ? ox : __expf(ox) - 1.f;
        oy = oy > 0.f ? oy : __expf(oy) - 1.f;
        oz = oz > 0.f ? oz : __expf(oz) - 1.f;
        ow = ow > 0.f ? ow : __expf(ow) - 1.f;
    }
    *(float4*)(out + (size_t)node * 128 + (lane << 2)) = make_float4(ox, oy, oz, ow);
}

// ---------------- host launcher ----------------
extern "C" void kernel_launch(void* const* d_in, const int* in_sizes, int n_in,
                              void* d_out, int out_size)
{
    const float* x     = (const float*)d_in[0];
    const int*   ei    = (const int*)  d_in[1];
    const float* W1l   = (const float*)d_in[2];
    const float* b1l   = (const float*)d_in[3];
    const float* W1r   = (const float*)d_in[4];
    const float* b1r   = (const float*)d_in[5];
    const float* att1  = (const float*)d_in[6];
    const float* bias1 = (const float*)d_in[7];
    const float* W2l   = (const float*)d_in[8];
    const float* b2l   = (const float*)d_in[9];
    const float* W2r   = (const float*)d_in[10];
    const float* b2r   = (const float*)d_in[11];
    const float* att2  = (const float*)d_in[12];
    const float* bias2 = (const float*)d_in[13];

    int N = in_sizes[0] / 128;
    int E = in_sizes[1] / 2;
    int tiles = (N + 127) / 128;

    void *p_xl, *p_xr, *p_h;
    cudaGetSymbolAddress(&p_xl, g_xl);
    cudaGetSymbolAddress(&p_xr, g_xr);
    cudaGetSymbolAddress(&p_h,  g_h);
    float* xl = (float*)p_xl;
    float* xr = (float*)p_xr;
    float* h  = (float*)p_h;

    static cudaStream_t s_csr = nullptr;
    static cudaEvent_t ev_fork = nullptr, ev_join = nullptr;
    static bool s_attr = false;
    if (s_csr == nullptr) {
        cudaStreamCreateWithFlags(&s_csr, cudaStreamNonBlocking);
        cudaEventCreateWithFlags(&ev_fork, cudaEventDisableTiming);
        cudaEventCreateWithFlags(&ev_join, cudaEventDisableTiming);
    }
    if (!s_attr) {
        cudaFuncSetAttribute(k_gemm_mma, cudaFuncAttributeMaxDynamicSharedMemorySize,
                             GEMM_SMEM_BYTES);
        s_attr = true;
    }

    const int TB = 256;
    int ablocks = (N * 32 + TB - 1) / TB;
    dim3 ggrid(tiles, 2);

    // Fork: CSR build on side stream, concurrent with layer-1 GEMM
    cudaEventRecord(ev_fork, 0);
    cudaStreamWaitEvent(s_csr, ev_fork, 0);
    k_zero_counts<<<(N + TB - 1) / TB, TB, 0, s_csr>>>(N);
    k_hist<<<(E + TB - 1) / TB, TB, 0, s_csr>>>(ei, E);
    k_scan<<<1, 1024, 0, s_csr>>>(N);
    k_scatter<<<(E + TB - 1) / TB, TB, 0, s_csr>>>(ei, E);
    cudaEventRecord(ev_join, s_csr);

    // Layer 1
    k_gemm_mma<<<ggrid, TB, GEMM_SMEM_BYTES>>>(x, W1l, b1l, xl, W1r, b1r, xr, N);
    cudaStreamWaitEvent(0, ev_join, 0);
    k_agg<false, true><<<ablocks, TB>>>(xl, xr, att1, bias1, h, N);

    // Layer 2
    k_gemm_mma<<<ggrid, TB, GEMM_SMEM_BYTES>>>(h, W2l, b2l, xl, W2r, b2r, xr, N);
    k_agg<true, false><<<ablocks, TB>>>(xl, xr, att2, bias2, (float*)d_out, N);
}

// round 6
// speedup vs baseline: 1.5497x; 1.1139x over previous
#include <cuda_runtime.h>
#include <cuda_bf16.h>
#include <math.h>
#include <stdint.h>

#define NMAX 50176
#define EMAX 800000

typedef unsigned long long u64;

// ---- device scratch (no runtime allocation allowed) ----
__device__ float g_xl[NMAX * 128];
__device__ float g_xr[NMAX * 128];
__device__ float g_h [NMAX * 128];
__device__ int   g_counts[NMAX];
__device__ int   g_rowptr[NMAX + 1];
__device__ int   g_cursor[NMAX];
__device__ int   g_csrc  [EMAX];
// precomputed W^T split-bf16, packed [n][k] row-major; slots: W1l,W1r,W2l,W2r
__device__ unsigned short g_Bh[4 * 16384];
__device__ unsigned short g_Bl[4 * 16384];

// ---------------- CSR build ----------------
__global__ void k_zero_counts(int n) {
    int i = blockIdx.x * blockDim.x + threadIdx.x;
    if (i < n) g_counts[i] = 0;
}

__global__ void k_hist(const int* __restrict__ ei, int E) {
    int e = blockIdx.x * blockDim.x + threadIdx.x;
    if (e < E) atomicAdd(&g_counts[ei[E + e]], 1);
}

__global__ void k_scan(int n) {
    __shared__ int part[1024];
    int tid = threadIdx.x;
    int chunk = (n + 1023) >> 10;
    int s0 = tid * chunk;
    int s1 = min(s0 + chunk, n);
    int s = 0;
    for (int i = s0; i < s1; i++) s += g_counts[i];
    part[tid] = s;
    __syncthreads();
    for (int off = 1; off < 1024; off <<= 1) {
        int v = (tid >= off) ? part[tid - off] : 0;
        __syncthreads();
        part[tid] += v;
        __syncthreads();
    }
    int base = (tid == 0) ? 0 : part[tid - 1];
    for (int i = s0; i < s1; i++) {
        g_rowptr[i] = base;
        g_cursor[i] = base;
        base += g_counts[i];
    }
    if (s1 == n) g_rowptr[n] = base;
}

__global__ void k_scatter(const int* __restrict__ ei, int E) {
    int e = blockIdx.x * blockDim.x + threadIdx.x;
    if (e < E) {
        int d = ei[E + e];
        int pos = atomicAdd(&g_cursor[d], 1);
        g_csrc[pos] = ei[e];
    }
}

// ---- split-bf16 helpers ----
__device__ __forceinline__ unsigned short bf_hi(float f) {
    return __bfloat16_as_ushort(__float2bfloat16(f));
}
__device__ __forceinline__ unsigned short bf_lo(float f, unsigned short hi) {
    float fh = __bfloat162float(__ushort_as_bfloat16(hi));
    return __bfloat16_as_ushort(__float2bfloat16(f - fh));
}

// ---------------- one-shot W conversion: all 4 weights -> B=W^T split bf16 ----
// Output packed [n][k] row-major per 16384-slot.
__global__ void k_cvtW_all(const float* __restrict__ W0, const float* __restrict__ W1,
                           const float* __restrict__ W2, const float* __restrict__ W3) {
    int idx = blockIdx.x * blockDim.x + threadIdx.x;   // 0 .. 65535
    int slot = idx >> 14;
    int rem = idx & 16383;
    int k = rem >> 7;
    int n = rem & 127;
    const float* W = (slot == 0) ? W0 : (slot == 1) ? W1 : (slot == 2) ? W2 : W3;
    float w = W[rem];                                  // coalesced [k][n] read
    unsigned short h = bf_hi(w);
    int off = (slot << 14) + (n << 7) + k;             // transposed packed write
    g_Bh[off] = h;
    g_Bl[off] = bf_lo(w, h);
}

// =================== split-bf16 HMMA GEMM ===================
// C{l,r}[M,128] = A[M,128] @ W{l,r}[128,128] + b  via  Ah*Bh + Ah*Bl + Al*Bh,
// fp32 accum (mma.sync m16n8k16 bf16). One CTA: 128x128x128; 8 warps 4(M)x2(N).
// A converted in-kernel; B copied from precomputed packed buffers.

#define PITCH 136                      // 272B rows: conflict-free ldmatrix
#define AS_H 0
#define AS_L (128 * PITCH)
#define BS_H (2 * 128 * PITCH)
#define BS_L (3 * 128 * PITCH)
#define GEMM_SMEM_BYTES (4 * 128 * PITCH * 2)

__device__ __forceinline__ uint32_t smem_u32(const void* p) {
    uint32_t a;
    asm("{ .reg .u64 t; cvta.to.shared.u64 t, %1; cvt.u32.u64 %0, t; }"
        : "=r"(a) : "l"(p));
    return a;
}

__device__ __forceinline__ void ldsm4(uint32_t& r0, uint32_t& r1, uint32_t& r2,
                                      uint32_t& r3, uint32_t addr) {
    asm volatile("ldmatrix.sync.aligned.m8n8.x4.shared.b16 {%0,%1,%2,%3}, [%4];"
        : "=r"(r0), "=r"(r1), "=r"(r2), "=r"(r3) : "r"(addr));
}

__device__ __forceinline__ void mma16816(float* c, uint32_t a0, uint32_t a1,
                                         uint32_t a2, uint32_t a3,
                                         uint32_t b0, uint32_t b1) {
    asm volatile(
        "mma.sync.aligned.m16n8k16.row.col.f32.bf16.bf16.f32 "
        "{%0,%1,%2,%3}, {%4,%5,%6,%7}, {%8,%9}, {%0,%1,%2,%3};"
        : "+f"(c[0]), "+f"(c[1]), "+f"(c[2]), "+f"(c[3])
        : "r"(a0), "r"(a1), "r"(a2), "r"(a3), "r"(b0), "r"(b1));
}

__global__ __launch_bounds__(256, 1) void k_gemm_mma(
    const float* __restrict__ A,
    const float* __restrict__ bl, float* __restrict__ Cl,
    const float* __restrict__ br, float* __restrict__ Cr,
    int slot0, int M)
{
    extern __shared__ __align__(16) unsigned short sm[];
    int sel = blockIdx.y;
    const float* bias = sel ? br : bl;
    float* C = sel ? Cr : Cl;
    int slot = slot0 + sel;

    int tid = threadIdx.x;
    int row0 = blockIdx.x << 7;

    // ---- stage A: fp32 [128,128] -> split bf16 smem, row-major, pitch 136 ----
    {
        const float4* A4 = (const float4*)(A + (size_t)row0 * 128);
#pragma unroll
        for (int i = 0; i < 16; i++) {
            int idx = tid + (i << 8);       // float4 index, 0..4095
            int r = idx >> 5;               // row 0..127
            int c = (idx & 31) << 2;        // col 0..124
            float4 v = (row0 + r < M) ? A4[idx] : make_float4(0.f, 0.f, 0.f, 0.f);
            ushort4 h, l;
            h.x = bf_hi(v.x); l.x = bf_lo(v.x, h.x);
            h.y = bf_hi(v.y); l.y = bf_lo(v.y, h.y);
            h.z = bf_hi(v.z); l.z = bf_lo(v.z, h.z);
            h.w = bf_hi(v.w); l.w = bf_lo(v.w, h.w);
            *(ushort4*)&sm[AS_H + r * PITCH + c] = h;
            *(ushort4*)&sm[AS_L + r * PITCH + c] = l;
        }
    }
    // ---- stage B: vectorized copy of precomputed packed [n][k] split tiles ----
    {
        const uint4* srcH = (const uint4*)(g_Bh + ((size_t)slot << 14));
        const uint4* srcL = (const uint4*)(g_Bl + ((size_t)slot << 14));
#pragma unroll
        for (int i = 0; i < 8; i++) {
            int v = tid + (i << 8);         // uint4 index 0..2047 (8 bf16 each)
            int e = v << 3;
            int n = e >> 7, k = e & 127;
            int d = n * PITCH + k;          // 16B-aligned (136%8==0, k%8==0)
            *(uint4*)&sm[BS_H + d] = srcH[v];
            *(uint4*)&sm[BS_L + d] = srcL[v];
        }
    }
    __syncthreads();

    int wid = tid >> 5, lane = tid & 31;
    int wm = (wid >> 1) << 5;    // warp m offset: 0,32,64,96
    int wn = (wid & 1) << 6;     // warp n offset: 0,64

    float acc[2][8][4];
#pragma unroll
    for (int mt = 0; mt < 2; mt++)
#pragma unroll
        for (int nt = 0; nt < 8; nt++)
#pragma unroll
            for (int q = 0; q < 4; q++) acc[mt][nt][q] = 0.f;

    int a_row = lane & 15;
    int a_col = (lane >> 4) << 3;
    int b_row = ((lane >> 4) << 3) + (lane & 7);
    int b_col = ((lane >> 3) & 1) << 3;

    uint32_t sb = smem_u32(sm);
    const int APASS[3] = {AS_H, AS_H, AS_L};
    const int BPASS[3] = {BS_H, BS_L, BS_H};

#pragma unroll
    for (int pass = 0; pass < 3; pass++) {
        uint32_t abase = sb + ((uint32_t)(APASS[pass] + (wm + a_row) * PITCH + a_col) << 1);
        uint32_t bbase = sb + ((uint32_t)(BPASS[pass] + (wn + b_row) * PITCH + b_col) << 1);
#pragma unroll
        for (int ks = 0; ks < 8; ks++) {
            int k0 = ks << 4;
            uint32_t af[2][4];
            ldsm4(af[0][0], af[0][1], af[0][2], af[0][3], abase + (k0 << 1));
            ldsm4(af[1][0], af[1][1], af[1][2], af[1][3],
                  abase + (k0 << 1) + (16 * PITCH << 1));
            uint32_t bf[4][4];
#pragma unroll
            for (int g = 0; g < 4; g++)
                ldsm4(bf[g][0], bf[g][1], bf[g][2], bf[g][3],
                      bbase + (k0 << 1) + ((g * 16 * PITCH) << 1));
#pragma unroll
            for (int mt = 0; mt < 2; mt++)
#pragma unroll
                for (int nt = 0; nt < 8; nt++) {
                    uint32_t b0 = bf[nt >> 1][(nt & 1) << 1];
                    uint32_t b1 = bf[nt >> 1][((nt & 1) << 1) + 1];
                    mma16816(acc[mt][nt], af[mt][0], af[mt][1], af[mt][2], af[mt][3], b0, b1);
                }
        }
    }

    // ---- epilogue: add bias, store fp32 ----
    int g = lane >> 2, tg = lane & 3;
#pragma unroll
    for (int mt = 0; mt < 2; mt++) {
        int rlo = row0 + wm + (mt << 4) + g;
        int rhi = rlo + 8;
#pragma unroll
        for (int nt = 0; nt < 8; nt++) {
            int col = wn + (nt << 3) + (tg << 1);
            float2 bv = *(const float2*)(bias + col);
            if (rlo < M) {
                float2 o = make_float2(acc[mt][nt][0] + bv.x, acc[mt][nt][1] + bv.y);
                *(float2*)(C + (size_t)rlo * 128 + col) = o;
            }
            if (rhi < M) {
                float2 o = make_float2(acc[mt][nt][2] + bv.x, acc[mt][nt][3] + bv.y);
                *(float2*)(C + (size_t)rhi * 128 + col) = o;
            }
        }
    }
}

// ---------------- GATv2 aggregation: one warp per destination node ----------------
template<bool FULLWARP, bool DOELU>
__global__ __launch_bounds__(256) void k_agg(
    const float* __restrict__ xl, const float* __restrict__ xr,
    const float* __restrict__ att, const float* __restrict__ bias,
    float* __restrict__ out, int n)
{
    int gw = (blockIdx.x * blockDim.x + threadIdx.x) >> 5;
    if (gw >= n) return;
    int lane = threadIdx.x & 31;
    int node = gw;

    float4 attv = *(const float4*)(att + (lane << 2));
    float4 xrv  = *(const float4*)(xr + (size_t)node * 128 + (lane << 2));

    int beg = g_rowptr[node];
    int cnt = g_rowptr[node + 1] - beg;

    float m = -3.402823466e38f;
    float denom = 0.f;
    float4 acc = make_float4(0.f, 0.f, 0.f, 0.f);

    const float4* xlp = (const float4*)xl;

    float4 v0 = xlp[(size_t)node * 32 + lane];
    float4 v1 = make_float4(0.f, 0.f, 0.f, 0.f);
    if (cnt > 0) v1 = xlp[(size_t)g_csrc[beg] * 32 + lane];

    int i = 0;
    while (true) {
        float4 v2 = make_float4(0.f, 0.f, 0.f, 0.f);
        if (i + 2 <= cnt) v2 = xlp[(size_t)g_csrc[beg + i + 1] * 32 + lane];

        float tx = v0.x + xrv.x; tx = tx > 0.f ? tx : 0.2f * tx;
        float ty = v0.y + xrv.y; ty = ty > 0.f ? ty : 0.2f * ty;
        float tz = v0.z + xrv.z; tz = tz > 0.f ? tz : 0.2f * tz;
        float tw = v0.w + xrv.w; tw = tw > 0.f ? tw : 0.2f * tw;
        float part = attv.x * tx + attv.y * ty + attv.z * tz + attv.w * tw;
        part += __shfl_xor_sync(0xffffffffu, part, 1);
        part += __shfl_xor_sync(0xffffffffu, part, 2);
        part += __shfl_xor_sync(0xffffffffu, part, 4);
        if (FULLWARP) {
            part += __shfl_xor_sync(0xffffffffu, part, 8);
            part += __shfl_xor_sync(0xffffffffu, part, 16);
        }

        float nm = fmaxf(m, part);
        float sc = __expf(m - nm);
        float p  = __expf(part - nm);
        denom = denom * sc + p;
        acc.x = fmaf(p, v0.x, acc.x * sc);
        acc.y = fmaf(p, v0.y, acc.y * sc);
        acc.z = fmaf(p, v0.z, acc.z * sc);
        acc.w = fmaf(p, v0.w, acc.w * sc);
        m = nm;

        if (++i > cnt) break;
        v0 = v1;
        v1 = v2;
    }

    float inv = 1.f / denom;
    float4 bv = *(const float4*)(bias + (lane << 2));
    float ox = fmaf(acc.x, inv, bv.x);
    float oy = fmaf(acc.y, inv, bv.y);
    float oz = fmaf(acc.z, inv, bv.z);
    float ow = fmaf(acc.w, inv, bv.w);
    if (DOELU) {
        ox = ox > 0.f ? ox : __expf(ox) - 1.f;
        oy = oy > 0.f ? oy : __expf(oy) - 1.f;
        oz = oz > 0.f ? oz : __expf(oz) - 1.f;
        ow = ow > 0.f ? ow : __expf(ow) - 1.f;
    }
    *(float4*)(out + (size_t)node * 128 + (lane << 2)) = make_float4(ox, oy, oz, ow);
}

// ---------------- host launcher ----------------
extern "C" void kernel_launch(void* const* d_in, const int* in_sizes, int n_in,
                              void* d_out, int out_size)
{
    const float* x     = (const float*)d_in[0];
    const int*   ei    = (const int*)  d_in[1];
    const float* W1l   = (const float*)d_in[2];
    const float* b1l   = (const float*)d_in[3];
    const float* W1r   = (const float*)d_in[4];
    const float* b1r   = (const float*)d_in[5];
    const float* att1  = (const float*)d_in[6];
    const float* bias1 = (const float*)d_in[7];
    const float* W2l   = (const float*)d_in[8];
    const float* b2l   = (const float*)d_in[9];
    const float* W2r   = (const float*)d_in[10];
    const float* b2r   = (const float*)d_in[11];
    const float* att2  = (const float*)d_in[12];
    const float* bias2 = (const float*)d_in[13];

    int N = in_sizes[0] / 128;
    int E = in_sizes[1] / 2;
    int tiles = (N + 127) / 128;

    void *p_xl, *p_xr, *p_h;
    cudaGetSymbolAddress(&p_xl, g_xl);
    cudaGetSymbolAddress(&p_xr, g_xr);
    cudaGetSymbolAddress(&p_h,  g_h);
    float* xl = (float*)p_xl;
    float* xr = (float*)p_xr;
    float* h  = (float*)p_h;

    static cudaStream_t s_csr = nullptr;
    static cudaEvent_t ev_fork = nullptr, ev_w = nullptr, ev_join = nullptr;
    static bool s_attr = false;
    if (s_csr == nullptr) {
        cudaStreamCreateWithFlags(&s_csr, cudaStreamNonBlocking);
        cudaEventCreateWithFlags(&ev_fork, cudaEventDisableTiming);
        cudaEventCreateWithFlags(&ev_w,    cudaEventDisableTiming);
        cudaEventCreateWithFlags(&ev_join, cudaEventDisableTiming);
    }
    if (!s_attr) {
        cudaFuncSetAttribute(k_gemm_mma, cudaFuncAttributeMaxDynamicSharedMemorySize,
                             GEMM_SMEM_BYTES);
        s_attr = true;
    }

    const int TB = 256;
    int ablocks = (N * 32 + TB - 1) / TB;
    dim3 ggrid(tiles, 2);

    // Fork: W conversion + CSR build on side stream
    cudaEventRecord(ev_fork, 0);
    cudaStreamWaitEvent(s_csr, ev_fork, 0);
    k_cvtW_all<<<256, TB, 0, s_csr>>>(W1l, W1r, W2l, W2r);
    cudaEventRecord(ev_w, s_csr);
    k_zero_counts<<<(N + TB - 1) / TB, TB, 0, s_csr>>>(N);
    k_hist<<<(E + TB - 1) / TB, TB, 0, s_csr>>>(ei, E);
    k_scan<<<1, 1024, 0, s_csr>>>(N);
    k_scatter<<<(E + TB - 1) / TB, TB, 0, s_csr>>>(ei, E);
    cudaEventRecord(ev_join, s_csr);

    // Layer 1
    cudaStreamWaitEvent(0, ev_w, 0);
    k_gemm_mma<<<ggrid, TB, GEMM_SMEM_BYTES>>>(x, b1l, xl, b1r, xr, 0, N);
    cudaStreamWaitEvent(0, ev_join, 0);
    k_agg<false, true><<<ablocks, TB>>>(xl, xr, att1, bias1, h, N);

    // Layer 2
    k_gemm_mma<<<ggrid, TB, GEMM_SMEM_BYTES>>>(h, b2l, xl, b2r, xr, 2, N);
    k_agg<true, false><<<ablocks, TB>>>(xl, xr, att2, bias2, (float*)d_out, N);
}

// round 7
// speedup vs baseline: 1.9874x; 1.2825x over previous
#include <cuda_runtime.h>
#include <cuda_bf16.h>
#include <math.h>
#include <stdint.h>

#define NMAX 50176
#define EMAX 800000

typedef unsigned long long u64;

// ---- device scratch (no runtime allocation allowed) ----
__device__ float g_xl[NMAX * 128];
__device__ float g_xr[NMAX * 128];
__device__ float g_h [NMAX * 128];
__device__ int   g_counts[NMAX];
__device__ int   g_incl  [NMAX];      // per-element inclusive scan (within block)
__device__ int   g_bsum  [64];        // per-block sums
__device__ int   g_boff  [64];        // exclusive block offsets
__device__ int   g_rowptr[NMAX + 1];
__device__ int   g_cursor[NMAX];
__device__ int   g_csrc  [EMAX];
// precomputed W^T split-bf16, packed [n][k] row-major; slots: W1l,W1r,W2l,W2r
__device__ unsigned short g_Bh[4 * 16384];
__device__ unsigned short g_Bl[4 * 16384];

// ---------------- CSR build ----------------
__global__ void k_zero_counts(int n) {
    int i = blockIdx.x * blockDim.x + threadIdx.x;
    if (i < n) g_counts[i] = 0;
}

__global__ void k_hist(const int* __restrict__ ei, int E) {
    int e = blockIdx.x * blockDim.x + threadIdx.x;
    if (e < E) atomicAdd(&g_counts[ei[E + e]], 1);
}

// level-1: per-block (1024 elems) inclusive scan + block sum
__global__ __launch_bounds__(1024) void k_scan1(int n) {
    __shared__ int sh[1024];
    int tid = threadIdx.x;
    int i = blockIdx.x * 1024 + tid;
    int v = (i < n) ? g_counts[i] : 0;
    sh[tid] = v;
    __syncthreads();
#pragma unroll
    for (int off = 1; off < 1024; off <<= 1) {
        int t = (tid >= off) ? sh[tid - off] : 0;
        __syncthreads();
        sh[tid] += t;
        __syncthreads();
    }
    if (i < n) g_incl[i] = sh[tid];
    if (tid == 1023) g_bsum[blockIdx.x] = sh[1023];
}

// level-2: scan the (<=64) block sums
__global__ void k_scan2(int nblocks) {
    __shared__ int sh[64];
    int tid = threadIdx.x;
    int v = (tid < nblocks) ? g_bsum[tid] : 0;
    sh[tid] = v;
    __syncthreads();
#pragma unroll
    for (int off = 1; off < 64; off <<= 1) {
        int t = (tid >= off) ? sh[tid - off] : 0;
        __syncthreads();
        sh[tid] += t;
        __syncthreads();
    }
    g_boff[tid] = sh[tid] - v;        // exclusive offset
}

// level-3: rowptr/cursor = global exclusive scan
__global__ __launch_bounds__(1024) void k_scan3(int n) {
    int i = blockIdx.x * 1024 + threadIdx.x;
    if (i < n) {
        int incl = g_incl[i] + g_boff[blockIdx.x];
        int excl = incl - g_counts[i];
        g_rowptr[i] = excl;
        g_cursor[i] = excl;
        if (i == n - 1) g_rowptr[n] = incl;
    }
}

__global__ void k_scatter(const int* __restrict__ ei, int E) {
    int e = blockIdx.x * blockDim.x + threadIdx.x;
    if (e < E) {
        int d = ei[E + e];
        int pos = atomicAdd(&g_cursor[d], 1);
        g_csrc[pos] = ei[e];
    }
}

// ---- split-bf16 helpers ----
__device__ __forceinline__ unsigned short bf_hi(float f) {
    return __bfloat16_as_ushort(__float2bfloat16(f));
}
__device__ __forceinline__ unsigned short bf_lo(float f, unsigned short hi) {
    float fh = __bfloat162float(__ushort_as_bfloat16(hi));
    return __bfloat16_as_ushort(__float2bfloat16(f - fh));
}

// ---------------- one-shot W conversion: all 4 weights -> B=W^T split bf16 ----
__global__ void k_cvtW_all(const float* __restrict__ W0, const float* __restrict__ W1,
                           const float* __restrict__ W2, const float* __restrict__ W3) {
    int idx = blockIdx.x * blockDim.x + threadIdx.x;   // 0 .. 65535
    int slot = idx >> 14;
    int rem = idx & 16383;
    int k = rem >> 7;
    int n = rem & 127;
    const float* W = (slot == 0) ? W0 : (slot == 1) ? W1 : (slot == 2) ? W2 : W3;
    float w = W[rem];
    unsigned short h = bf_hi(w);
    int off = (slot << 14) + (n << 7) + k;
    g_Bh[off] = h;
    g_Bl[off] = bf_lo(w, h);
}

// =================== split-bf16 HMMA GEMM ===================
#define PITCH 136
#define AS_H 0
#define AS_L (128 * PITCH)
#define BS_H (2 * 128 * PITCH)
#define BS_L (3 * 128 * PITCH)
#define GEMM_SMEM_BYTES (4 * 128 * PITCH * 2)

__device__ __forceinline__ uint32_t smem_u32(const void* p) {
    uint32_t a;
    asm("{ .reg .u64 t; cvta.to.shared.u64 t, %1; cvt.u32.u64 %0, t; }"
        : "=r"(a) : "l"(p));
    return a;
}

__device__ __forceinline__ void ldsm4(uint32_t& r0, uint32_t& r1, uint32_t& r2,
                                      uint32_t& r3, uint32_t addr) {
    asm volatile("ldmatrix.sync.aligned.m8n8.x4.shared.b16 {%0,%1,%2,%3}, [%4];"
        : "=r"(r0), "=r"(r1), "=r"(r2), "=r"(r3) : "r"(addr));
}

__device__ __forceinline__ void mma16816(float* c, uint32_t a0, uint32_t a1,
                                         uint32_t a2, uint32_t a3,
                                         uint32_t b0, uint32_t b1) {
    asm volatile(
        "mma.sync.aligned.m16n8k16.row.col.f32.bf16.bf16.f32 "
        "{%0,%1,%2,%3}, {%4,%5,%6,%7}, {%8,%9}, {%0,%1,%2,%3};"
        : "+f"(c[0]), "+f"(c[1]), "+f"(c[2]), "+f"(c[3])
        : "r"(a0), "r"(a1), "r"(a2), "r"(a3), "r"(b0), "r"(b1));
}

__global__ __launch_bounds__(256, 1) void k_gemm_mma(
    const float* __restrict__ A,
    const float* __restrict__ bl, float* __restrict__ Cl,
    const float* __restrict__ br, float* __restrict__ Cr,
    int slot0, int M)
{
    extern __shared__ __align__(16) unsigned short sm[];
    int sel = blockIdx.y;
    const float* bias = sel ? br : bl;
    float* C = sel ? Cr : Cl;
    int slot = slot0 + sel;

    int tid = threadIdx.x;
    int row0 = blockIdx.x << 7;

    // ---- stage A: fp32 -> split bf16 smem ----
    {
        const float4* A4 = (const float4*)(A + (size_t)row0 * 128);
#pragma unroll
        for (int i = 0; i < 16; i++) {
            int idx = tid + (i << 8);
            int r = idx >> 5;
            int c = (idx & 31) << 2;
            float4 v = (row0 + r < M) ? A4[idx] : make_float4(0.f, 0.f, 0.f, 0.f);
            ushort4 h, l;
            h.x = bf_hi(v.x); l.x = bf_lo(v.x, h.x);
            h.y = bf_hi(v.y); l.y = bf_lo(v.y, h.y);
            h.z = bf_hi(v.z); l.z = bf_lo(v.z, h.z);
            h.w = bf_hi(v.w); l.w = bf_lo(v.w, h.w);
            *(ushort4*)&sm[AS_H + r * PITCH + c] = h;
            *(ushort4*)&sm[AS_L + r * PITCH + c] = l;
        }
    }
    // ---- stage B: vectorized copy of packed tiles ----
    {
        const uint4* srcH = (const uint4*)(g_Bh + ((size_t)slot << 14));
        const uint4* srcL = (const uint4*)(g_Bl + ((size_t)slot << 14));
#pragma unroll
        for (int i = 0; i < 8; i++) {
            int v = tid + (i << 8);
            int e = v << 3;
            int n = e >> 7, k = e & 127;
            int d = n * PITCH + k;
            *(uint4*)&sm[BS_H + d] = srcH[v];
            *(uint4*)&sm[BS_L + d] = srcL[v];
        }
    }
    __syncthreads();

    int wid = tid >> 5, lane = tid & 31;
    int wm = (wid >> 1) << 5;
    int wn = (wid & 1) << 6;

    float acc[2][8][4];
#pragma unroll
    for (int mt = 0; mt < 2; mt++)
#pragma unroll
        for (int nt = 0; nt < 8; nt++)
#pragma unroll
            for (int q = 0; q < 4; q++) acc[mt][nt][q] = 0.f;

    int a_row = lane & 15;
    int a_col = (lane >> 4) << 3;
    int b_row = ((lane >> 4) << 3) + (lane & 7);
    int b_col = ((lane >> 3) & 1) << 3;

    uint32_t sb = smem_u32(sm);
    const int APASS[3] = {AS_H, AS_H, AS_L};
    const int BPASS[3] = {BS_H, BS_L, BS_H};

#pragma unroll
    for (int pass = 0; pass < 3; pass++) {
        uint32_t abase = sb + ((uint32_t)(APASS[pass] + (wm + a_row) * PITCH + a_col) << 1);
        uint32_t bbase = sb + ((uint32_t)(BPASS[pass] + (wn + b_row) * PITCH + b_col) << 1);
#pragma unroll
        for (int ks = 0; ks < 8; ks++) {
            int k0 = ks << 4;
            uint32_t af[2][4];
            ldsm4(af[0][0], af[0][1], af[0][2], af[0][3], abase + (k0 << 1));
            ldsm4(af[1][0], af[1][1], af[1][2], af[1][3],
                  abase + (k0 << 1) + (16 * PITCH << 1));
            uint32_t bf[4][4];
#pragma unroll
            for (int g = 0; g < 4; g++)
                ldsm4(bf[g][0], bf[g][1], bf[g][2], bf[g][3],
                      bbase + (k0 << 1) + ((g * 16 * PITCH) << 1));
#pragma unroll
            for (int mt = 0; mt < 2; mt++)
#pragma unroll
                for (int nt = 0; nt < 8; nt++) {
                    uint32_t b0 = bf[nt >> 1][(nt & 1) << 1];
                    uint32_t b1 = bf[nt >> 1][((nt & 1) << 1) + 1];
                    mma16816(acc[mt][nt], af[mt][0], af[mt][1], af[mt][2], af[mt][3], b0, b1);
                }
        }
    }

    int g = lane >> 2, tg = lane & 3;
#pragma unroll
    for (int mt = 0; mt < 2; mt++) {
        int rlo = row0 + wm + (mt << 4) + g;
        int rhi = rlo + 8;
#pragma unroll
        for (int nt = 0; nt < 8; nt++) {
            int col = wn + (nt << 3) + (tg << 1);
            float2 bv = *(const float2*)(bias + col);
            if (rlo < M) {
                float2 o = make_float2(acc[mt][nt][0] + bv.x, acc[mt][nt][1] + bv.y);
                *(float2*)(C + (size_t)rlo * 128 + col) = o;
            }
            if (rhi < M) {
                float2 o = make_float2(acc[mt][nt][2] + bv.x, acc[mt][nt][3] + bv.y);
                *(float2*)(C + (size_t)rhi * 128 + col) = o;
            }
        }
    }
}

// ---------------- GATv2 aggregation: one warp per destination node ----------------
template<bool FULLWARP, bool DOELU>
__global__ __launch_bounds__(256) void k_agg(
    const float* __restrict__ xl, const float* __restrict__ xr,
    const float* __restrict__ att, const float* __restrict__ bias,
    float* __restrict__ out, int n)
{
    int gw = (blockIdx.x * blockDim.x + threadIdx.x) >> 5;
    if (gw >= n) return;
    int lane = threadIdx.x & 31;
    int node = gw;

    float4 attv = *(const float4*)(att + (lane << 2));
    float4 xrv  = *(const float4*)(xr + (size_t)node * 128 + (lane << 2));

    int beg = g_rowptr[node];
    int cnt = g_rowptr[node + 1] - beg;

    float m = -3.402823466e38f;
    float denom = 0.f;
    float4 acc = make_float4(0.f, 0.f, 0.f, 0.f);

    const float4* xlp = (const float4*)xl;

    float4 v0 = xlp[(size_t)node * 32 + lane];
    float4 v1 = make_float4(0.f, 0.f, 0.f, 0.f);
    if (cnt > 0) v1 = xlp[(size_t)g_csrc[beg] * 32 + lane];

    int i = 0;
    while (true) {
        float4 v2 = make_float4(0.f, 0.f, 0.f, 0.f);
        if (i + 2 <= cnt) v2 = xlp[(size_t)g_csrc[beg + i + 1] * 32 + lane];

        float tx = v0.x + xrv.x; tx = tx > 0.f ? tx : 0.2f * tx;
        float ty = v0.y + xrv.y; ty = ty > 0.f ? ty : 0.2f * ty;
        float tz = v0.z + xrv.z; tz = tz > 0.f ? tz : 0.2f * tz;
        float tw = v0.w + xrv.w; tw = tw > 0.f ? tw : 0.2f * tw;
        float part = attv.x * tx + attv.y * ty + attv.z * tz + attv.w * tw;
        part += __shfl_xor_sync(0xffffffffu, part, 1);
        part += __shfl_xor_sync(0xffffffffu, part, 2);
        part += __shfl_xor_sync(0xffffffffu, part, 4);
        if (FULLWARP) {
            part += __shfl_xor_sync(0xffffffffu, part, 8);
            part += __shfl_xor_sync(0xffffffffu, part, 16);
        }

        float nm = fmaxf(m, part);
        float sc = __expf(m - nm);
        float p  = __expf(part - nm);
        denom = denom * sc + p;
        acc.x = fmaf(p, v0.x, acc.x * sc);
        acc.y = fmaf(p, v0.y, acc.y * sc);
        acc.z = fmaf(p, v0.z, acc.z * sc);
        acc.w = fmaf(p, v0.w, acc.w * sc);
        m = nm;

        if (++i > cnt) break;
        v0 = v1;
        v1 = v2;
    }

    float inv = 1.f / denom;
    float4 bv = *(const float4*)(bias + (lane << 2));
    float ox = fmaf(acc.x, inv, bv.x);
    float oy = fmaf(acc.y, inv, bv.y);
    float oz = fmaf(acc.z, inv, bv.z);
    float ow = fmaf(acc.w, inv, bv.w);
    if (DOELU) {
        ox = ox > 0.f ? ox : __expf(ox) - 1.f;
        oy = oy > 0.f ? oy : __expf(oy) - 1.f;
        oz = oz > 0.f ? oz : __expf(oz) - 1.f;
        ow = ow > 0.f ? ow : __expf(ow) - 1.f;
    }
    *(float4*)(out + (size_t)node * 128 + (lane << 2)) = make_float4(ox, oy, oz, ow);
}

// ---------------- host launcher ----------------
extern "C" void kernel_launch(void* const* d_in, const int* in_sizes, int n_in,
                              void* d_out, int out_size)
{
    const float* x     = (const float*)d_in[0];
    const int*   ei    = (const int*)  d_in[1];
    const float* W1l   = (const float*)d_in[2];
    const float* b1l   = (const float*)d_in[3];
    const float* W1r   = (const float*)d_in[4];
    const float* b1r   = (const float*)d_in[5];
    const float* att1  = (const float*)d_in[6];
    const float* bias1 = (const float*)d_in[7];
    const float* W2l   = (const float*)d_in[8];
    const float* b2l   = (const float*)d_in[9];
    const float* W2r   = (const float*)d_in[10];
    const float* b2r   = (const float*)d_in[11];
    const float* att2  = (const float*)d_in[12];
    const float* bias2 = (const float*)d_in[13];

    int N = in_sizes[0] / 128;
    int E = in_sizes[1] / 2;
    int tiles = (N + 127) / 128;
    int sblocks = (N + 1023) / 1024;

    void *p_xl, *p_xr, *p_h;
    cudaGetSymbolAddress(&p_xl, g_xl);
    cudaGetSymbolAddress(&p_xr, g_xr);
    cudaGetSymbolAddress(&p_h,  g_h);
    float* xl = (float*)p_xl;
    float* xr = (float*)p_xr;
    float* h  = (float*)p_h;

    static cudaStream_t s_csr = nullptr;
    static cudaEvent_t ev_fork = nullptr, ev_w = nullptr, ev_join = nullptr;
    static bool s_attr = false;
    if (s_csr == nullptr) {
        cudaStreamCreateWithFlags(&s_csr, cudaStreamNonBlocking);
        cudaEventCreateWithFlags(&ev_fork, cudaEventDisableTiming);
        cudaEventCreateWithFlags(&ev_w,    cudaEventDisableTiming);
        cudaEventCreateWithFlags(&ev_join, cudaEventDisableTiming);
    }
    if (!s_attr) {
        cudaFuncSetAttribute(k_gemm_mma, cudaFuncAttributeMaxDynamicSharedMemorySize,
                             GEMM_SMEM_BYTES);
        s_attr = true;
    }

    const int TB = 256;
    int ablocks = (N * 32 + TB - 1) / TB;
    dim3 ggrid(tiles, 2);

    // Fork: W conversion + CSR build on side stream
    cudaEventRecord(ev_fork, 0);
    cudaStreamWaitEvent(s_csr, ev_fork, 0);
    k_cvtW_all<<<256, TB, 0, s_csr>>>(W1l, W1r, W2l, W2r);
    cudaEventRecord(ev_w, s_csr);
    k_zero_counts<<<(N + TB - 1) / TB, TB, 0, s_csr>>>(N);
    k_hist<<<(E + TB - 1) / TB, TB, 0, s_csr>>>(ei, E);
    k_scan1<<<sblocks, 1024, 0, s_csr>>>(N);
    k_scan2<<<1, 64, 0, s_csr>>>(sblocks);
    k_scan3<<<sblocks, 1024, 0, s_csr>>>(N);
    k_scatter<<<(E + TB - 1) / TB, TB, 0, s_csr>>>(ei, E);
    cudaEventRecord(ev_join, s_csr);

    // Layer 1
    cudaStreamWaitEvent(0, ev_w, 0);
    k_gemm_mma<<<ggrid, TB, GEMM_SMEM_BYTES>>>(x, b1l, xl, b1r, xr, 0, N);
    cudaStreamWaitEvent(0, ev_join, 0);
    k_agg<false, true><<<ablocks, TB>>>(xl, xr, att1, bias1, h, N);

    // Layer 2
    k_gemm_mma<<<ggrid, TB, GEMM_SMEM_BYTES>>>(h, b2l, xl, b2r, xr, 2, N);
    k_agg<true, false><<<ablocks, TB>>>(xl, xr, att2, bias2, (float*)d_out, N);
}